// round 11
// baseline (speedup 1.0000x reference)
#include <cuda_runtime.h>
#include <cstdint>
#include <cstddef>

#define B_ 16
#define C_ 512
#define N_ 4096
#define K_ 32
#define NT_ 32                // n-tiles (128 n each)

// Scratch (device globals — allocation-free rule)
__device__ float g_part[B_ * NT_ * K_ * 512];   // [b][nt][k][c] 32 MB partials
__device__ float g_as[B_ * K_ * NT_];           // per-ntile Asum partials

__device__ __forceinline__ uint32_t tf32_of(float a) {
    uint32_t r;
    asm("{ .reg .b32 t; cvt.rna.tf32.f32 t, %1; mov.b32 %0, t; }" : "=r"(r) : "f"(a));
    return r;
}
__device__ __forceinline__ void mma16888(float* d, const uint32_t* a, const uint32_t* b) {
    asm volatile(
        "mma.sync.aligned.m16n8k8.row.col.f32.tf32.tf32.f32 "
        "{%0,%1,%2,%3}, {%4,%5,%6,%7}, {%8,%9}, {%0,%1,%2,%3};"
        : "+f"(d[0]), "+f"(d[1]), "+f"(d[2]), "+f"(d[3])
        : "r"(a[0]), "r"(a[1]), "r"(a[2]), "r"(a[3]), "r"(b[0]), "r"(b[1]));
}

// =====================================================================
// KF: fused logits+softmax (phase 1, = R10 k1) and enc partial GEMM
// (phase 2, = k3 logic with A read straight from smem Ao).
// grid (32 n-tiles, 16 b), 256 threads (8 warps).
// smem: x_s 2x[32*136] 34816 | cw_s 2x[32*36] 9216 | Ao 32x132 16896 |
//       sq 4096 | x2 512 | sc/c2 256 | as 1024  ~ 66.8 KB -> 3 CTAs/SM
// =====================================================================
__global__ void __launch_bounds__(256) kf_fused(const float* __restrict__ x,
                                                const float* __restrict__ cw,
                                                const float* __restrict__ scale) {
    __shared__ uint32_t x_s[2][32 * 136];
    __shared__ uint32_t cw_s[2][32 * 36];
    __shared__ uint32_t Ao_s[32 * 132];       // A[k][n_local] tf32
    __shared__ float sq_s[256 * 4];
    __shared__ float x2_s[128];
    __shared__ float sc_s[K_], c2_s[K_];
    __shared__ float as_s[8 * K_];

    const int tid  = threadIdx.x;
    const int lane = tid & 31, w = tid >> 5;
    const int b    = blockIdx.y;
    const int n0   = blockIdx.x * 128;
    const int ar0  = lane >> 2, an0 = lane & 3;

    if (tid < 32) sc_s[tid] = scale[tid];

    // ================= PHASE 1: logits + softmax =================
    const int cst = tid >> 5;              // x: c sub-row 0..7
    const int nq4 = lane * 4;              // x: n offset
    const int kk  = tid >> 3;              // cw: k row 0..31
    const int cq  = tid & 7;               // cw: col quad 0..7

    const float* xg  = x  + (size_t)b * C_ * N_ + n0;
    const float* cwg = cw + kk * C_ + cq * 4;

    float sq[4] = {0.f, 0.f, 0.f, 0.f};
    float c2p = 0.f;
    float acc[4][4];
    #pragma unroll
    for (int nt = 0; nt < 4; nt++)
        #pragma unroll
        for (int j = 0; j < 4; j++) acc[nt][j] = 0.f;

    float4 xr[4], cwr;
    #pragma unroll
    for (int j = 0; j < 4; j++)
        xr[j] = *(const float4*)(xg + (size_t)(cst + 8 * j) * N_ + nq4);
    cwr = *(const float4*)(cwg);
    {
        #pragma unroll
        for (int j = 0; j < 4; j++) {
            float4 v = xr[j];
            sq[0] += v.x * v.x; sq[1] += v.y * v.y;
            sq[2] += v.z * v.z; sq[3] += v.w * v.w;
            *(uint4*)(&x_s[0][(cst + 8 * j) * 136 + nq4]) =
                make_uint4(tf32_of(v.x), tf32_of(v.y), tf32_of(v.z), tf32_of(v.w));
        }
        uint4 u = make_uint4(tf32_of(cwr.x), tf32_of(cwr.y), tf32_of(cwr.z), tf32_of(cwr.w));
        float t0 = __uint_as_float(u.x), t1 = __uint_as_float(u.y);
        float t2 = __uint_as_float(u.z), t3 = __uint_as_float(u.w);
        c2p += t0 * t0 + t1 * t1 + t2 * t2 + t3 * t3;
        *(uint4*)(&cw_s[0][kk * 36 + cq * 4]) = u;
    }
    #pragma unroll
    for (int j = 0; j < 4; j++)
        xr[j] = *(const float4*)(xg + (size_t)(32 + cst + 8 * j) * N_ + nq4);
    cwr = *(const float4*)(cwg + 32);
    __syncthreads();

    for (int ch = 0; ch < 16; ch++) {
        if (ch < 15) {
            const int nbuf = (ch + 1) & 1;
            #pragma unroll
            for (int j = 0; j < 4; j++) {
                float4 v = xr[j];
                sq[0] += v.x * v.x; sq[1] += v.y * v.y;
                sq[2] += v.z * v.z; sq[3] += v.w * v.w;
                *(uint4*)(&x_s[nbuf][(cst + 8 * j) * 136 + nq4]) =
                    make_uint4(tf32_of(v.x), tf32_of(v.y), tf32_of(v.z), tf32_of(v.w));
            }
            uint4 u = make_uint4(tf32_of(cwr.x), tf32_of(cwr.y),
                                 tf32_of(cwr.z), tf32_of(cwr.w));
            float t0 = __uint_as_float(u.x), t1 = __uint_as_float(u.y);
            float t2 = __uint_as_float(u.z), t3 = __uint_as_float(u.w);
            c2p += t0 * t0 + t1 * t1 + t2 * t2 + t3 * t3;
            *(uint4*)(&cw_s[nbuf][kk * 36 + cq * 4]) = u;
        }
        if (ch < 14) {
            #pragma unroll
            for (int j = 0; j < 4; j++)
                xr[j] = *(const float4*)(xg +
                    (size_t)((ch + 2) * 32 + cst + 8 * j) * N_ + nq4);
            cwr = *(const float4*)(cwg + (ch + 2) * 32);
        }
        const uint32_t* xb   = x_s[ch & 1];
        const uint32_t* cb_s = cw_s[ch & 1];
        #pragma unroll
        for (int ks = 0; ks < 4; ks++) {
            const int cb = ks * 8;
            uint32_t af[4];
            const uint32_t* ap = xb + (cb + an0) * 136 + 16 * w + ar0;
            af[0] = ap[0];
            af[1] = ap[8];
            af[2] = ap[4 * 136];
            af[3] = ap[4 * 136 + 8];
            #pragma unroll
            for (int nt = 0; nt < 4; nt++) {
                uint32_t bf[2];
                const uint32_t* bp = cb_s + (8 * nt + ar0) * 36 + cb + an0;
                bf[0] = bp[0];
                bf[1] = bp[4];
                mma16888(acc[nt], af, bf);
            }
        }
        __syncthreads();
    }

    // c2 reduce (8 consecutive lanes per k)
    c2p += __shfl_down_sync(0xffffffffu, c2p, 4, 8);
    c2p += __shfl_down_sync(0xffffffffu, c2p, 2, 8);
    c2p += __shfl_down_sync(0xffffffffu, c2p, 1, 8);
    if (cq == 0) c2_s[kk] = c2p;

    // x2 reduce (exact fp32)
    *(float4*)(sq_s + tid * 4) = make_float4(sq[0], sq[1], sq[2], sq[3]);
    __syncthreads();
    if (tid < 128) {
        float s = 0.f;
        #pragma unroll
        for (int g = 0; g < 8; g++) s += sq_s[(g * 32 + (tid >> 2)) * 4 + (tid & 3)];
        x2_s[tid] = s;
    }
    __syncthreads();

    // logits + softmax
    const float x2r0 = x2_s[16 * w + ar0];
    const float x2r1 = x2_s[16 * w + ar0 + 8];
    float lg0[8], lg1[8];
    float m0 = -1e30f, m1 = -1e30f;
    #pragma unroll
    for (int nt = 0; nt < 4; nt++) {
        #pragma unroll
        for (int j = 0; j < 2; j++) {
            const int k = 8 * nt + 2 * an0 + j;
            const float sck = sc_s[k], c2k = c2_s[k];
            float a = sck * (x2r0 - 2.f * acc[nt][j]     + c2k);
            float c = sck * (x2r1 - 2.f * acc[nt][2 + j] + c2k);
            lg0[nt * 2 + j] = a; lg1[nt * 2 + j] = c;
            m0 = fmaxf(m0, a); m1 = fmaxf(m1, c);
        }
    }
    m0 = fmaxf(m0, __shfl_xor_sync(0xffffffffu, m0, 1));
    m0 = fmaxf(m0, __shfl_xor_sync(0xffffffffu, m0, 2));
    m1 = fmaxf(m1, __shfl_xor_sync(0xffffffffu, m1, 1));
    m1 = fmaxf(m1, __shfl_xor_sync(0xffffffffu, m1, 2));
    float s0 = 0.f, s1 = 0.f;
    #pragma unroll
    for (int i = 0; i < 8; i++) {
        lg0[i] = __expf(lg0[i] - m0); s0 += lg0[i];
        lg1[i] = __expf(lg1[i] - m1); s1 += lg1[i];
    }
    s0 += __shfl_xor_sync(0xffffffffu, s0, 1);
    s0 += __shfl_xor_sync(0xffffffffu, s0, 2);
    s1 += __shfl_xor_sync(0xffffffffu, s1, 1);
    s1 += __shfl_xor_sync(0xffffffffu, s1, 2);
    const float inv0 = 1.f / s0, inv1 = 1.f / s1;

    // Asum partials over this CTA's 128 n
    float akp[8];
    #pragma unroll
    for (int i = 0; i < 8; i++) akp[i] = lg0[i] * inv0 + lg1[i] * inv1;
    #pragma unroll
    for (int off = 4; off < 32; off <<= 1)
        #pragma unroll
        for (int i = 0; i < 8; i++)
            akp[i] += __shfl_xor_sync(0xffffffffu, akp[i], off);
    if (ar0 == 0) {
        #pragma unroll
        for (int nt = 0; nt < 4; nt++)
            #pragma unroll
            for (int j = 0; j < 2; j++)
                as_s[w * 32 + 8 * nt + 2 * an0 + j] = akp[nt * 2 + j];
    }

    // A -> Ao_s[k][n_local] as tf32 (consumed directly as phase-2 fragments)
    #pragma unroll
    for (int nt = 0; nt < 4; nt++) {
        #pragma unroll
        for (int j = 0; j < 2; j++) {
            const int k = 8 * nt + 2 * an0 + j;
            Ao_s[k * 132 + 16 * w + ar0]     = tf32_of(lg0[nt * 2 + j] * inv0);
            Ao_s[k * 132 + 16 * w + ar0 + 8] = tf32_of(lg1[nt * 2 + j] * inv1);
        }
    }
    __syncthreads();
    if (tid < 32) {
        float s = 0.f;
        #pragma unroll
        for (int ww = 0; ww < 8; ww++) s += as_s[ww * 32 + tid];
        g_as[(b * K_ + tid) * NT_ + blockIdx.x] = s;
    }

    // ================= PHASE 2: enc partials =================
    // D[32k x 512c] = sum over this CTA's 128 n of A[k,n]*x[c,n].
    // 8 c-groups of 64 c; per group 4 n-chunks of 32 n staged [64c][32n] pad36.
    const int sr = tid >> 1;      // staging row 0..63 (tid<128)
    const int sh = tid & 1;       // n-half (16 n)
    float* pb = g_part + ((size_t)(b * NT_ + blockIdx.x) * K_) * 512;
    const int dr = lane >> 2;
    const int dc = (lane & 3) * 2;

    for (int cg = 0; cg < 8; cg++) {
        float a2[2][4];
        #pragma unroll
        for (int mt = 0; mt < 2; mt++)
            #pragma unroll
            for (int j = 0; j < 4; j++) a2[mt][j] = 0.f;

        float4 pr[4];
        if (tid < 128) {
            const float* src = xg + (size_t)(cg * 64 + sr) * N_ + sh * 16;
            #pragma unroll
            for (int j = 0; j < 4; j++) pr[j] = *(const float4*)(src + 4 * j);
        }
        for (int nc = 0; nc < 4; nc++) {
            uint32_t* xp = x_s[nc & 1];
            if (tid < 128) {
                uint32_t* xd = xp + sr * 36 + sh * 16;
                #pragma unroll
                for (int j = 0; j < 4; j++)
                    *(uint4*)(xd + 4 * j) =
                        make_uint4(tf32_of(pr[j].x), tf32_of(pr[j].y),
                                   tf32_of(pr[j].z), tf32_of(pr[j].w));
            }
            __syncthreads();
            if (tid < 128 && nc < 3) {
                const float* src = xg + (size_t)(cg * 64 + sr) * N_ + (nc + 1) * 32 + sh * 16;
                #pragma unroll
                for (int j = 0; j < 4; j++) pr[j] = *(const float4*)(src + 4 * j);
            }
            #pragma unroll
            for (int ks = 0; ks < 4; ks++) {
                const int nk = ks * 8;
                uint32_t af[2][4], bf[2];
                #pragma unroll
                for (int mt = 0; mt < 2; mt++) {
                    const uint32_t* ap = Ao_s + (mt * 16 + ar0) * 132 + nc * 32 + nk + an0;
                    af[mt][0] = ap[0];
                    af[mt][1] = ap[8 * 132];
                    af[mt][2] = ap[4];
                    af[mt][3] = ap[8 * 132 + 4];
                }
                const uint32_t* bp = xp + (w * 8 + ar0) * 36 + nk + an0;
                bf[0] = bp[0];
                bf[1] = bp[4];
                #pragma unroll
                for (int mt = 0; mt < 2; mt++) mma16888(a2[mt], af[mt], bf);
            }
            __syncthreads();
        }
        // write partials for this c-group
        const int c0 = cg * 64 + w * 8 + dc;
        #pragma unroll
        for (int mt = 0; mt < 2; mt++) {
            *(float2*)(pb + (mt * 16 + dr) * 512 + c0) =
                make_float2(a2[mt][0], a2[mt][1]);
            *(float2*)(pb + (mt * 16 + dr + 8) * 512 + c0) =
                make_float2(a2[mt][2], a2[mt][3]);
        }
    }
}

// =====================================================================
// K4: per (b,k): Asum from g_as + reduce 32 ntile partials + final.
// grid 512 blocks, 128 threads.
// =====================================================================
__global__ void k4_final(float* __restrict__ out, const float* __restrict__ cw) {
    __shared__ float s_asum;
    const int bk  = blockIdx.x;
    const int b   = bk >> 5, k = bk & 31;
    const int tid = threadIdx.x;

    if (tid < 32) {
        float v = g_as[bk * NT_ + tid];
        #pragma unroll
        for (int o = 16; o; o >>= 1) v += __shfl_down_sync(0xffffffffu, v, o);
        if (tid == 0) s_asum = v;
    }
    __syncthreads();
    const float asum = s_asum;

    #pragma unroll
    for (int j = 0; j < 4; j++) {
        const int c = tid + j * 128;
        float v = 0.f;
        #pragma unroll
        for (int nt = 0; nt < NT_; nt++)
            v += g_part[((size_t)(b * NT_ + nt) * K_ + k) * 512 + c];
        out[(size_t)bk * C_ + c] = v - asum * cw[k * C_ + c];
    }
}

// =====================================================================
extern "C" void kernel_launch(void* const* d_in, const int* in_sizes, int n_in,
                              void* d_out, int out_size) {
    const float* x     = (const float*)d_in[0];
    const float* cw    = (const float*)d_in[1];
    const float* scale = (const float*)d_in[2];
    float* out = (float*)d_out;

    kf_fused<<<dim3(NT_, B_), 256>>>(x, cw, scale);
    k4_final<<<B_ * K_, 128>>>(out, cw);
}

// round 12
// speedup vs baseline: 1.9634x; 1.9634x over previous
#include <cuda_runtime.h>
#include <cstdint>
#include <cstddef>

#define B_ 16
#define C_ 512
#define N_ 4096
#define K_ 32
#define NS_ 8                 // K3 n-splits (512 n each)
#define CT_ 4                 // K3 c-tiles (128 c each)
#define NT_ 32                // K1 n-tiles (128 n each)

// Scratch (device globals — allocation-free rule)
__device__ float g_A[B_ * K_ * N_];                       // [b][k][n] tf32-rounded, 8 MB
__device__ float g_part[B_ * NS_ * CT_ * K_ * 128];       // 8 MB partials
__device__ float g_as[B_ * K_ * NT_];                     // per-ntile Asum partials

__device__ __forceinline__ uint32_t tf32_of(float a) {
    uint32_t r;
    asm("{ .reg .b32 t; cvt.rna.tf32.f32 t, %1; mov.b32 %0, t; }" : "=r"(r) : "f"(a));
    return r;
}
__device__ __forceinline__ void mma16888(float* d, const uint32_t* a, const uint32_t* b) {
    asm volatile(
        "mma.sync.aligned.m16n8k8.row.col.f32.tf32.tf32.f32 "
        "{%0,%1,%2,%3}, {%4,%5,%6,%7}, {%8,%9}, {%0,%1,%2,%3};"
        : "+f"(d[0]), "+f"(d[1]), "+f"(d[2]), "+f"(d[3])
        : "r"(a[0]), "r"(a[1]), "r"(a[2]), "r"(a[3]), "r"(b[0]), "r"(b[1]));
}
__device__ __forceinline__ uint32_t smem_u32(const void* p) {
    uint32_t a;
    asm("{ .reg .u64 t; cvta.to.shared.u64 t, %1; cvt.u32.u64 %0, t; }" : "=r"(a) : "l"(p));
    return a;
}
__device__ __forceinline__ void cpa16(uint32_t dst, const void* src) {
    asm volatile("cp.async.cg.shared.global [%0], [%1], 16;" :: "r"(dst), "l"(src));
}
__device__ __forceinline__ void cpa_commit() {
    asm volatile("cp.async.commit_group;" ::: "memory");
}
__device__ __forceinline__ void cpa_wait1() {
    asm volatile("cp.async.wait_group 1;" ::: "memory");
}
__device__ __forceinline__ void cpa_wait0() {
    asm volatile("cp.async.wait_group 0;" ::: "memory");
}

// =====================================================================
// K1: logits + softmax via mma.sync tf32, cp.async 3-stage x ring.
// grid (32 n-tiles, 16 b), 256 threads (8 warps, warp owns 16 n).
// dyn smem: x ring 3x17408 @0 | cw 2x4608 @52224 | sc @61440 |
//           c2 @61568 | as @61696  -> 62720 B.  Ao reuses stage 0.
// x2 accumulated from raw fp32 fragments; rna cvt at fragment time.
// A written to g_A pre-rounded to tf32 (k3 consumes raw).
// =====================================================================
#define K1_SMEM 62720

__global__ void __launch_bounds__(256) k1_softmax(const float* __restrict__ x,
                                                  const float* __restrict__ cw,
                                                  const float* __restrict__ scale) {
    extern __shared__ char sm[];
    const uint32_t smb = smem_u32(sm);
    uint32_t* cw_s = (uint32_t*)(sm + 52224);
    float*    sc_s = (float*)(sm + 61440);
    float*    c2_s = (float*)(sm + 61568);
    float*    as_s = (float*)(sm + 61696);

    const int tid  = threadIdx.x;
    const int lane = tid & 31, w = tid >> 5;
    const int b    = blockIdx.y;
    const int n0   = blockIdx.x * 128;
    const int ar0  = lane >> 2, an0 = lane & 3;

    if (tid < 32) sc_s[tid] = scale[tid];

    const int cst = tid >> 5;              // x stage: c sub-row 0..7
    const int nq4 = lane * 4;              // x stage: n offset
    const int kk  = tid >> 3;              // cw: k row
    const int cq  = tid & 7;               // cw: col quad

    const float* xg  = x  + (size_t)b * C_ * N_ + n0;
    const float* cwg = cw + kk * C_ + cq * 4;

    float c2p = 0.f;
    float sq0 = 0.f, sq1 = 0.f;
    float acc[4][4];
    #pragma unroll
    for (int nt = 0; nt < 4; nt++)
        #pragma unroll
        for (int j = 0; j < 4; j++) acc[nt][j] = 0.f;

    // ---- prologue: async-issue x chunks 0,1; stage cw0; prefetch cw1 ----
    #pragma unroll
    for (int s = 0; s < 2; s++) {
        const uint32_t dstb = smb + s * 17408;
        #pragma unroll
        for (int j = 0; j < 4; j++)
            cpa16(dstb + ((cst + 8 * j) * 136 + nq4) * 4,
                  xg + (size_t)(s * 32 + cst + 8 * j) * N_ + nq4);
        cpa_commit();
    }
    float4 cwr = *(const float4*)(cwg);
    {
        uint4 u = make_uint4(tf32_of(cwr.x), tf32_of(cwr.y), tf32_of(cwr.z), tf32_of(cwr.w));
        float t0 = __uint_as_float(u.x), t1 = __uint_as_float(u.y);
        float t2 = __uint_as_float(u.z), t3 = __uint_as_float(u.w);
        c2p += t0 * t0 + t1 * t1 + t2 * t2 + t3 * t3;
        *(uint4*)(cw_s + kk * 36 + cq * 4) = u;
    }
    cwr = *(const float4*)(cwg + 32);
    cpa_wait1();
    __syncthreads();

    // ---- mainloop: 16 chunks of 32 c ----
    for (int ch = 0; ch < 16; ch++) {
        if (ch < 14) {
            const uint32_t dstb = smb + ((ch + 2) % 3) * 17408;
            #pragma unroll
            for (int j = 0; j < 4; j++)
                cpa16(dstb + ((cst + 8 * j) * 136 + nq4) * 4,
                      xg + (size_t)((ch + 2) * 32 + cst + 8 * j) * N_ + nq4);
            cpa_commit();
        }
        if (ch < 15) {
            uint4 u = make_uint4(tf32_of(cwr.x), tf32_of(cwr.y),
                                 tf32_of(cwr.z), tf32_of(cwr.w));
            float t0 = __uint_as_float(u.x), t1 = __uint_as_float(u.y);
            float t2 = __uint_as_float(u.z), t3 = __uint_as_float(u.w);
            c2p += t0 * t0 + t1 * t1 + t2 * t2 + t3 * t3;
            *(uint4*)(cw_s + ((ch + 1) & 1) * 1152 + kk * 36 + cq * 4) = u;
        }
        if (ch < 14) cwr = *(const float4*)(cwg + (ch + 2) * 32);

        const uint32_t* xb   = (const uint32_t*)(sm + (ch % 3) * 17408);
        const uint32_t* cb_s = cw_s + (ch & 1) * 1152;
        #pragma unroll
        for (int ks = 0; ks < 4; ks++) {
            const int cb = ks * 8;
            const uint32_t* ap = xb + (cb + an0) * 136 + 16 * w + ar0;
            const float f0 = __uint_as_float(ap[0]);
            const float f1 = __uint_as_float(ap[8]);
            const float f2 = __uint_as_float(ap[4 * 136]);
            const float f3 = __uint_as_float(ap[4 * 136 + 8]);
            sq0 += f0 * f0 + f2 * f2;
            sq1 += f1 * f1 + f3 * f3;
            uint32_t af[4];
            af[0] = tf32_of(f0); af[1] = tf32_of(f1);
            af[2] = tf32_of(f2); af[3] = tf32_of(f3);
            #pragma unroll
            for (int nt = 0; nt < 4; nt++) {
                uint32_t bf[2];
                const uint32_t* bp = cb_s + (8 * nt + ar0) * 36 + cb + an0;
                bf[0] = bp[0];
                bf[1] = bp[4];
                mma16888(acc[nt], af, bf);
            }
        }
        if (ch < 14) cpa_wait1(); else cpa_wait0();
        __syncthreads();
    }

    // ---- c2 reduce (8 consecutive lanes per k) ----
    c2p += __shfl_down_sync(0xffffffffu, c2p, 4, 8);
    c2p += __shfl_down_sync(0xffffffffu, c2p, 2, 8);
    c2p += __shfl_down_sync(0xffffffffu, c2p, 1, 8);
    if (cq == 0) c2_s[kk] = c2p;
    __syncthreads();

    // ---- x2 via shfl over the an0 quad (exact fp32) ----
    float x2r0 = sq0, x2r1 = sq1;
    x2r0 += __shfl_xor_sync(0xffffffffu, x2r0, 1);
    x2r0 += __shfl_xor_sync(0xffffffffu, x2r0, 2);
    x2r1 += __shfl_xor_sync(0xffffffffu, x2r1, 1);
    x2r1 += __shfl_xor_sync(0xffffffffu, x2r1, 2);

    // ---- logits + softmax ----
    float lg0[8], lg1[8];
    float m0 = -1e30f, m1 = -1e30f;
    #pragma unroll
    for (int nt = 0; nt < 4; nt++) {
        #pragma unroll
        for (int j = 0; j < 2; j++) {
            const int k = 8 * nt + 2 * an0 + j;
            const float sck = sc_s[k], c2k = c2_s[k];
            float a = sck * (x2r0 - 2.f * acc[nt][j]     + c2k);
            float c = sck * (x2r1 - 2.f * acc[nt][2 + j] + c2k);
            lg0[nt * 2 + j] = a; lg1[nt * 2 + j] = c;
            m0 = fmaxf(m0, a); m1 = fmaxf(m1, c);
        }
    }
    m0 = fmaxf(m0, __shfl_xor_sync(0xffffffffu, m0, 1));
    m0 = fmaxf(m0, __shfl_xor_sync(0xffffffffu, m0, 2));
    m1 = fmaxf(m1, __shfl_xor_sync(0xffffffffu, m1, 1));
    m1 = fmaxf(m1, __shfl_xor_sync(0xffffffffu, m1, 2));
    float s0 = 0.f, s1 = 0.f;
    #pragma unroll
    for (int i = 0; i < 8; i++) {
        lg0[i] = __expf(lg0[i] - m0); s0 += lg0[i];
        lg1[i] = __expf(lg1[i] - m1); s1 += lg1[i];
    }
    s0 += __shfl_xor_sync(0xffffffffu, s0, 1);
    s0 += __shfl_xor_sync(0xffffffffu, s0, 2);
    s1 += __shfl_xor_sync(0xffffffffu, s1, 1);
    s1 += __shfl_xor_sync(0xffffffffu, s1, 2);
    const float inv0 = 1.f / s0, inv1 = 1.f / s1;

    // ---- Asum partials (exact fp32) ----
    float akp[8];
    #pragma unroll
    for (int i = 0; i < 8; i++) akp[i] = lg0[i] * inv0 + lg1[i] * inv1;
    #pragma unroll
    for (int off = 4; off < 32; off <<= 1)
        #pragma unroll
        for (int i = 0; i < 8; i++)
            akp[i] += __shfl_xor_sync(0xffffffffu, akp[i], off);
    if (ar0 == 0) {
        #pragma unroll
        for (int nt = 0; nt < 4; nt++)
            #pragma unroll
            for (int j = 0; j < 2; j++)
                as_s[w * 32 + 8 * nt + 2 * an0 + j] = akp[nt * 2 + j];
    }

    // ---- A (pre-rounded tf32) -> smem transpose -> coalesced STG ----
    uint32_t* Ao = (uint32_t*)sm;                 // [32 k][132 n-pad], reuses stage 0
    #pragma unroll
    for (int nt = 0; nt < 4; nt++) {
        #pragma unroll
        for (int j = 0; j < 2; j++) {
            const int k = 8 * nt + 2 * an0 + j;
            Ao[k * 132 + 16 * w + ar0]     = tf32_of(lg0[nt * 2 + j] * inv0);
            Ao[k * 132 + 16 * w + ar0 + 8] = tf32_of(lg1[nt * 2 + j] * inv1);
        }
    }
    __syncthreads();
    if (tid < 32) {
        float s = 0.f;
        #pragma unroll
        for (int ww = 0; ww < 8; ww++) s += as_s[ww * 32 + tid];
        g_as[(b * K_ + tid) * NT_ + blockIdx.x] = s;
    }
    float* ag = g_A + (size_t)(b * K_) * N_ + n0;
    #pragma unroll
    for (int t = 0; t < 4; t++) {
        int f = tid + t * 256;                    // 0..1023
        int k = f >> 5, nq = (f & 31) * 4;
        *(uint4*)(ag + (size_t)k * N_ + nq) = *(uint4*)(Ao + k * 132 + nq);
    }
}

// =====================================================================
// K3: enc partial via mma.sync tf32, cp.async 3-stage rings for x and A.
// D[32k x 128c] += sum_n A[k,n] * x[c,n] over 512 n per CTA.
// grid (CT_=4, NS_=8, B_=16), 256 threads.
// dyn smem: x ring 3x18432 @0 | A ring 3x4608 @55296 -> 69120 B.
// A arrives pre-rounded tf32 (raw fragment use); x rna-cvt at fragment.
// =====================================================================
#define K3_SMEM 69120

__global__ void __launch_bounds__(256) k3_enc(const float* __restrict__ x) {
    extern __shared__ char sm[];
    const uint32_t smb = smem_u32(sm);

    const int tid   = threadIdx.x;
    const int lane  = tid & 31, w = tid >> 5;
    const int ctile = blockIdx.x;
    const int ns    = blockIdx.y;
    const int b     = blockIdx.z;
    const int cwarp = w * 16;
    const int ar0   = lane >> 2, an0 = lane & 3;

    const float* xg = x   + ((size_t)(b * C_) + ctile * 128) * N_;
    const float* ag = g_A + ((size_t)b * K_) * N_;
    const int nb0 = ns * 512;

    const int xc = tid >> 1;      // c row 0..127 (x stage)
    const int xh = tid & 1;       // n-half (16 n)
    const int ak = tid >> 3;      // k row (A stage)
    const int aq = tid & 7;       // n quad

    float acc[2][2][4];
    #pragma unroll
    for (int mt = 0; mt < 2; mt++)
        #pragma unroll
        for (int ct = 0; ct < 2; ct++)
            #pragma unroll
            for (int j = 0; j < 4; j++) acc[mt][ct][j] = 0.f;

    // ---- prologue: async-issue chunks 0,1 ----
    #pragma unroll
    for (int s = 0; s < 2; s++) {
        const int nb = nb0 + s * 32;
        const uint32_t xdst = smb + s * 18432;
        #pragma unroll
        for (int j = 0; j < 4; j++)
            cpa16(xdst + (xc * 36 + xh * 16 + 4 * j) * 4,
                  xg + (size_t)xc * N_ + nb + xh * 16 + 4 * j);
        cpa16(smb + 55296 + s * 4608 + (ak * 36 + aq * 4) * 4,
              ag + (size_t)ak * N_ + nb + aq * 4);
        cpa_commit();
    }
    cpa_wait1();
    __syncthreads();

    // ---- mainloop: 16 chunks of 32 n ----
    for (int ch = 0; ch < 16; ch++) {
        if (ch < 14) {
            const int nb = nb0 + (ch + 2) * 32;
            const int st = (ch + 2) % 3;
            const uint32_t xdst = smb + st * 18432;
            #pragma unroll
            for (int j = 0; j < 4; j++)
                cpa16(xdst + (xc * 36 + xh * 16 + 4 * j) * 4,
                      xg + (size_t)xc * N_ + nb + xh * 16 + 4 * j);
            cpa16(smb + 55296 + st * 4608 + (ak * 36 + aq * 4) * 4,
                  ag + (size_t)ak * N_ + nb + aq * 4);
            cpa_commit();
        }
        const uint32_t* As = (const uint32_t*)(sm + 55296 + (ch % 3) * 4608);
        const uint32_t* Xs = (const uint32_t*)(sm + (ch % 3) * 18432);
        #pragma unroll
        for (int ks = 0; ks < 4; ks++) {
            const int nk = ks * 8;
            uint32_t af[2][4], bf[2][2];
            #pragma unroll
            for (int mt = 0; mt < 2; mt++) {
                const uint32_t* ap = As + (mt * 16 + ar0) * 36 + nk + an0;
                af[mt][0] = ap[0];                 // already tf32 bits
                af[mt][1] = ap[8 * 36];
                af[mt][2] = ap[4];
                af[mt][3] = ap[8 * 36 + 4];
            }
            #pragma unroll
            for (int ct = 0; ct < 2; ct++) {
                const uint32_t* bp = Xs + (cwarp + ct * 8 + ar0) * 36 + nk + an0;
                bf[ct][0] = tf32_of(__uint_as_float(bp[0]));
                bf[ct][1] = tf32_of(__uint_as_float(bp[4]));
            }
            #pragma unroll
            for (int mt = 0; mt < 2; mt++)
                #pragma unroll
                for (int ct = 0; ct < 2; ct++)
                    mma16888(acc[mt][ct], af[mt], bf[ct]);
        }
        if (ch < 14) cpa_wait1(); else cpa_wait0();
        __syncthreads();
    }

    // ---- epilogue -> g_part[b][ns][ctile][k][c] ----
    float* pb = g_part + (((size_t)(b * NS_ + ns) * CT_ + ctile) << 12);
    const int dr = lane >> 2;
    const int dc = (lane & 3) * 2;
    #pragma unroll
    for (int mt = 0; mt < 2; mt++) {
        #pragma unroll
        for (int ct = 0; ct < 2; ct++) {
            const int c0 = cwarp + ct * 8 + dc;
            const int r0 = mt * 16 + dr;
            *(float2*)(pb + r0 * 128 + c0) =
                make_float2(acc[mt][ct][0], acc[mt][ct][1]);
            *(float2*)(pb + (r0 + 8) * 128 + c0) =
                make_float2(acc[mt][ct][2], acc[mt][ct][3]);
        }
    }
}

// =====================================================================
// K4: per (b,k): Asum from g_as partials + combine + subtract Asum*cw.
// =====================================================================
__global__ void k4_final(float* __restrict__ out, const float* __restrict__ cw) {
    __shared__ float s_asum;
    const int bk  = blockIdx.x;
    const int b   = bk >> 5, k = bk & 31;
    const int tid = threadIdx.x;

    if (tid < 32) {
        float v = g_as[bk * NT_ + tid];
        #pragma unroll
        for (int o = 16; o; o >>= 1) v += __shfl_down_sync(0xffffffffu, v, o);
        if (tid == 0) s_asum = v;
    }
    __syncthreads();
    const float asum = s_asum;

    #pragma unroll
    for (int j = 0; j < 4; j++) {
        const int c  = tid + j * 128;
        const int ct = c >> 7, cl = c & 127;
        float v = 0.f;
        #pragma unroll
        for (int sp = 0; sp < NS_; sp++)
            v += g_part[(((size_t)(b * NS_ + sp) * CT_ + ct) << 12) + k * 128 + cl];
        out[(size_t)bk * C_ + c] = v - asum * cw[k * C_ + c];
    }
}

// =====================================================================
extern "C" void kernel_launch(void* const* d_in, const int* in_sizes, int n_in,
                              void* d_out, int out_size) {
    const float* x     = (const float*)d_in[0];
    const float* cw    = (const float*)d_in[1];
    const float* scale = (const float*)d_in[2];
    float* out = (float*)d_out;

    cudaFuncSetAttribute(k1_softmax, cudaFuncAttributeMaxDynamicSharedMemorySize, K1_SMEM);
    cudaFuncSetAttribute(k3_enc,     cudaFuncAttributeMaxDynamicSharedMemorySize, K3_SMEM);

    k1_softmax<<<dim3(NT_, B_), 256, K1_SMEM>>>(x, cw, scale);
    k3_enc<<<dim3(CT_, NS_, B_), 256, K3_SMEM>>>(x);
    k4_final<<<B_ * K_, 128>>>(out, cw);
}